// round 10
// baseline (speedup 1.0000x reference)
#include <cuda_runtime.h>

#define BN    2048
#define DD    32
#define NIDS  8192
#define KNN   30
#define TI    8
#define JPT   4
#define NTHR  256
#define JH    (NTHR * JPT)              // 1024
#define YSPL  2
#define XCTA  (BN / TI)                 // 256
#define NCTAS_ALL (XCTA * (YSPL + 1))   // 768
#define BCAP  32

// Scratch (no allocations allowed)
__device__ float g_sq[BN];
__device__ __align__(16) unsigned long long g_zTp[DD * BN];  // (v,v) duplicated pairs
__device__ float g_pden[YSPL * BN];
__device__ float g_num[BN];
__device__ float g_any[BN];
__device__ float g_diag[BN];
__device__ int   g_bkt[NIDS * BCAP];
__device__ int   g_bcnt[NIDS];          // zero-init at load; re-zeroed by main's last block
__device__ unsigned g_cnt = 0;

__device__ __forceinline__ unsigned long long pack2(float x, float y) {
    unsigned long long r;
    asm("mov.b64 %0, {%1, %2};" : "=l"(r) : "f"(x), "f"(y));
    return r;
}
__device__ __forceinline__ void unpack2(unsigned long long v, float &x, float &y) {
    asm("mov.b64 {%0, %1}, %2;" : "=f"(x), "=f"(y) : "l"(v));
}
__device__ __forceinline__ unsigned long long fma2(unsigned long long a,
                                                   unsigned long long b,
                                                   unsigned long long c) {
    unsigned long long d;
    asm("fma.rn.f32x2 %0, %1, %2, %3;" : "=l"(d) : "l"(a), "l"(b), "l"(c));
    return d;
}
__device__ __forceinline__ float fsqrt_approx(float x) {
    float r;
    asm("sqrt.approx.f32 %0, %1;" : "=f"(r) : "f"(x));
    return r;
}
// shared expression so den-path and sparse/diag-path codegen matches bit-exactly
__device__ __forceinline__ float pair_e(float dot, float sqsum) {
    float d2 = fmaf(-2.f, dot, sqsum);
    d2 = fmaxf(d2, 1e-20f);
    return __expf(-fsqrt_approx(d2));
}

// Kernel 1: grid 264 CTAs.
//  bid<256 : transpose z -> duplicated zTp + row norms (coalesced).
//  bid>=256: atomic bucket fill  id -> {j : sid[j]==id}  (order nondet; sorted at use).
__global__ void __launch_bounds__(NTHR)
prep_kernel(const float* __restrict__ z, const int* __restrict__ sid) {
    __shared__ float sf[8 * 33];
    const int t = threadIdx.x;

    if (blockIdx.x < 256) {
        const int idx = blockIdx.x * NTHR + t;
        const float v = __ldg(&z[idx]);
        float s = v * v;
#pragma unroll
        for (int off = 16; off > 0; off >>= 1)
            s += __shfl_xor_sync(0xffffffffu, s, off);
        if ((t & 31) == 0) g_sq[idx >> 5] = s;
        sf[(t >> 5) * 33 + (t & 31)] = v;
        __syncthreads();
        const int k2 = t >> 3;
        const int jo = t & 7;
        float vt = sf[jo * 33 + k2];
        g_zTp[k2 * BN + blockIdx.x * 8 + jo] = pack2(vt, vt);
    } else {
        const int j = (blockIdx.x - 256) * NTHR + t;   // 8 CTAs cover 2048 j's
        const int id = sid[j];
        int slot = atomicAdd(&g_bcnt[id], 1);
        if (slot < BCAP) g_bkt[id * BCAP + slot] = j;
    }
}

// Kernel 2: grid (256, 3).
//  y<2 : den slice — rows [x*8,+8) vs j in [y*1024,+1024), 4 j's/thread.
//        Hot loop: 2 LDG.128 (pre-duplicated j ops) + 2 LDS.128 (z_i pairs, 1-deep
//        prefetch) + 16 FFMA2 per k. No packs, no mask.
//  y==2: sparse num/valid/diag via inverse buckets — warp per row.
// Last of 768 CTAs: final scalar reduction + scratch reset.
__global__ void __launch_bounds__(NTHR, 3)
main_kernel(const float* __restrict__ z,
            const int* __restrict__ knn,
            const int* __restrict__ sid,
            float* __restrict__ out) {
    // z_i row-pairs: u64 index k*4+p = (zi[2p][k], zi[2p+1][k]) -> 1KB, 16B-aligned rows
    __shared__ __align__(16) unsigned long long s_zi[DD * (TI / 2)];
    __shared__ float s_sqi[TI];
    __shared__ float s_rd[NTHR / 32][TI];
    __shared__ bool s_last;

    const int t = threadIdx.x;
    const int y = blockIdx.y;
    const int warp = t >> 5, lane = t & 31;

    if (y < YSPL) {
        const int row0 = blockIdx.x * TI;
        const int j0 = y * JH;
        {   // fill z_i tile (256 floats): sf[k*TI + r]
            float* sf = (float*)s_zi;
            int k = t & 31, r = t >> 5;
            sf[k * TI + r] = z[(row0 + r) * DD + k];
        }
        if (t < TI) s_sqi[t] = g_sq[row0 + t];
        __syncthreads();

        const int j = j0 + t * JPT;
        unsigned long long acc[TI / 2][JPT];
#pragma unroll
        for (int p = 0; p < TI / 2; p++)
#pragma unroll
            for (int q = 0; q < JPT; q++) acc[p][q] = 0ull;

        // LDG pipeline: duplicated j-operands, 2x ulonglong2 per k, depth 4
        const ulonglong2* pj = (const ulonglong2*)(g_zTp + j);  // stride BN/2 per k
        ulonglong2 bufA[4], bufB[4];
#pragma unroll
        for (int k = 0; k < 4; k++) {
            bufA[k] = pj[k * (BN / 2)];
            bufB[k] = pj[k * (BN / 2) + 1];
        }
        // LDS pipeline: 1-deep prefetch of z_i row-pairs
        ulonglong2 z01 = *(const ulonglong2*)&s_zi[0];
        ulonglong2 z23 = *(const ulonglong2*)&s_zi[2];

#pragma unroll
        for (int k = 0; k < DD; k++) {
            ulonglong2 cz01 = z01, cz23 = z23;
            if (k + 1 < DD) {
                z01 = *(const ulonglong2*)&s_zi[(k + 1) * 4 + 0];
                z23 = *(const ulonglong2*)&s_zi[(k + 1) * 4 + 2];
            }
            ulonglong2 va = bufA[k & 3];   // (v_j0|v_j0 , v_j1|v_j1)
            ulonglong2 vb = bufB[k & 3];   // (v_j2|v_j2 , v_j3|v_j3)
            if (k + 4 < DD) {
                bufA[k & 3] = pj[(k + 4) * (BN / 2)];
                bufB[k & 3] = pj[(k + 4) * (BN / 2) + 1];
            }

            acc[0][0] = fma2(cz01.x, va.x, acc[0][0]);
            acc[0][1] = fma2(cz01.x, va.y, acc[0][1]);
            acc[0][2] = fma2(cz01.x, vb.x, acc[0][2]);
            acc[0][3] = fma2(cz01.x, vb.y, acc[0][3]);
            acc[1][0] = fma2(cz01.y, va.x, acc[1][0]);
            acc[1][1] = fma2(cz01.y, va.y, acc[1][1]);
            acc[1][2] = fma2(cz01.y, vb.x, acc[1][2]);
            acc[1][3] = fma2(cz01.y, vb.y, acc[1][3]);
            acc[2][0] = fma2(cz23.x, va.x, acc[2][0]);
            acc[2][1] = fma2(cz23.x, va.y, acc[2][1]);
            acc[2][2] = fma2(cz23.x, vb.x, acc[2][2]);
            acc[2][3] = fma2(cz23.x, vb.y, acc[2][3]);
            acc[3][0] = fma2(cz23.y, va.x, acc[3][0]);
            acc[3][1] = fma2(cz23.y, va.y, acc[3][1]);
            acc[3][2] = fma2(cz23.y, vb.x, acc[3][2]);
            acc[3][3] = fma2(cz23.y, vb.y, acc[3][3]);
        }

        const float4 sqjv = *(const float4*)(g_sq + j);
        const float sqj[JPT] = {sqjv.x, sqjv.y, sqjv.z, sqjv.w};
        float den[TI];
#pragma unroll
        for (int p = 0; p < TI / 2; p++) {
            float d0[JPT], d1[JPT];
#pragma unroll
            for (int q = 0; q < JPT; q++) unpack2(acc[p][q], d0[q], d1[q]);
#pragma unroll
            for (int rr = 0; rr < 2; rr++) {
                int r = 2 * p + rr;
                float base = s_sqi[r];
                float e0 = pair_e(rr ? d1[0] : d0[0], base + sqj[0]);
                float e1 = pair_e(rr ? d1[1] : d0[1], base + sqj[1]);
                float e2 = pair_e(rr ? d1[2] : d0[2], base + sqj[2]);
                float e3 = pair_e(rr ? d1[3] : d0[3], base + sqj[3]);
                den[r] = (e0 + e1) + (e2 + e3);   // includes diag term; subtracted later
            }
        }
#pragma unroll
        for (int r = 0; r < TI; r++) {
#pragma unroll
            for (int off = 16; off > 0; off >>= 1)
                den[r] += __shfl_xor_sync(0xffffffffu, den[r], off);
        }
        if (lane == 0) {
#pragma unroll
            for (int r = 0; r < TI; r++) s_rd[warp][r] = den[r];
        }
        __syncthreads();
        if (t < TI) {
            float dsum = 0.f;
#pragma unroll
            for (int w = 0; w < NTHR / 32; w++) dsum += s_rd[w][t];
            g_pden[y * BN + row0 + t] = dsum;
        }
    } else {
        // ---- sparse num / valid / diag: warp per row (cold path) ----
        const int i = blockIdx.x * TI + warp;
        const int sidi = sid[i];
        int id = (lane < KNN) ? knn[sidi * KNN + lane] : -1;
        bool dup = false;
#pragma unroll
        for (int p = 0; p < KNN; p++) {
            int idp = __shfl_sync(0xffffffffu, id, p);
            dup = dup || (p < lane && idp == id);
        }
        float num = 0.f;
        bool found = false;
        if (lane < KNN && !dup) {
            int cnt = g_bcnt[id];
            if (cnt > BCAP) cnt = BCAP;
            if (cnt > 0) {
                int jarr[BCAP];
                for (int s = 0; s < cnt; s++) jarr[s] = g_bkt[id * BCAP + s];
                // insertion sort ascending -> deterministic summation order
                for (int a = 1; a < cnt; a++) {
                    int v = jarr[a];
                    int b = a - 1;
                    while (b >= 0 && jarr[b] > v) { jarr[b + 1] = jarr[b]; b--; }
                    jarr[b + 1] = v;
                }
                for (int s = 0; s < cnt; s++) {
                    int jj = jarr[s];
                    if (jj != i) {
                        const float* zi = z + i * DD;
                        const float* zj = z + jj * DD;
                        float dot = 0.f;
#pragma unroll
                        for (int k = 0; k < DD; k++) dot = fmaf(zi[k], zj[k], dot);
                        num += pair_e(dot, g_sq[i] + g_sq[jj]);
                        found = true;
                    }
                }
            }
        }
#pragma unroll
        for (int off = 16; off > 0; off >>= 1)
            num += __shfl_xor_sync(0xffffffffu, num, off);
        unsigned bal = __ballot_sync(0xffffffffu, found);
        if (lane == 0) {
            // e_ii: sequential fmaf chain == FFMA2 lane chain bit-exactly
            const float* zi = z + i * DD;
            float dot = 0.f;
#pragma unroll
            for (int k = 0; k < DD; k++) dot = fmaf(zi[k], zi[k], dot);
            g_diag[i] = pair_e(dot, g_sq[i] + g_sq[i]);
            g_num[i] = num;
            g_any[i] = bal ? 1.f : 0.f;
        }
    }

    // ---- last-block final reduction (deterministic) ----
    __threadfence();
    if (t == 0) {
        unsigned old = atomicAdd(&g_cnt, 1u);
        s_last = (old == NCTAS_ALL - 1);
    }
    __syncthreads();
    if (!s_last) return;

    __threadfence();
    float tot = 0.f, cnt = 0.f;
#pragma unroll
    for (int i = t; i < BN; i += NTHR) {
        float den = (__ldcg(&g_pden[i]) + __ldcg(&g_pden[BN + i])) - __ldcg(&g_diag[i]);
        float nv = __ldcg(&g_num[i]);
        bool valid = __ldcg(&g_any[i]) > 0.f;
        float sr = nv / den;
        float loss = -__logf(sr + 1e-8f);
        tot += valid ? loss : 0.f;
        cnt += valid ? 1.f : 0.f;
    }
#pragma unroll
    for (int off = 16; off > 0; off >>= 1) {
        tot += __shfl_xor_sync(0xffffffffu, tot, off);
        cnt += __shfl_xor_sync(0xffffffffu, cnt, off);
    }
    if (lane == 0) { s_rd[warp][0] = tot; s_rd[warp][1] = cnt; }
    __syncthreads();
    if (t == 0) {
        float T = 0.f, C = 0.f;
#pragma unroll
        for (int w = 0; w < NTHR / 32; w++) { T += s_rd[w][0]; C += s_rd[w][1]; }
        out[0] = (C > 0.f) ? (T / C) : 0.f;
        g_cnt = 0;
    }
    // reset bucket counters for the next replay (zero-init covers the first call)
    for (int i = t; i < NIDS; i += NTHR) g_bcnt[i] = 0;
}

extern "C" void kernel_launch(void* const* d_in, const int* in_sizes, int n_in,
                              void* d_out, int out_size) {
    const float* z   = (const float*)d_in[0];
    const int*   knn = (const int*)d_in[1];
    const int*   sid = (const int*)d_in[2];
    (void)in_sizes; (void)n_in; (void)out_size;

    prep_kernel<<<256 + BN / NTHR, NTHR>>>(z, sid);
    main_kernel<<<dim3(XCTA, YSPL + 1, 1), NTHR>>>(z, knn, sid, (float*)d_out);
}

// round 12
// speedup vs baseline: 1.0621x; 1.0621x over previous
#include <cuda_runtime.h>
#include <cuda_bf16.h>
#include <cstdint>

#define BN    2048
#define DD    32
#define NIDS  8192
#define KNN   30
#define NTHR  256
#define MT    128
#define NT    128
#define XT    (BN / MT)         // 16
#define YT    (BN / NT)         // 16
#define SPY   8
#define NCTAS_ALL (XT * (YT + SPY))  // 384
#define BCAP  32
#define RS    144               // smem row stride bytes: 128B data (hi|lo) + 16B pad

// Scratch (no allocations allowed)
__device__ float g_sq[BN];
__device__ __align__(16) unsigned g_zhl[BN * 32];  // 128B/row: 16 u32 hi | 16 u32 lo
__device__ float g_pden[YT * BN];
__device__ float g_num[BN];
__device__ float g_any[BN];
__device__ int   g_bkt[NIDS * BCAP];
__device__ int   g_bcnt[NIDS];
__device__ unsigned g_cnt = 0;

__device__ __forceinline__ float fsqrt_approx(float x) {
    float r; asm("sqrt.approx.f32 %0, %1;" : "=f"(r) : "f"(x)); return r;
}
__device__ __forceinline__ float pair_e(float dot, float sqsum) {
    float d2 = fmaf(-2.f, dot, sqsum);
    d2 = fmaxf(d2, 1e-20f);
    return __expf(-fsqrt_approx(d2));
}
__device__ __forceinline__ uint32_t bpack(__nv_bfloat16 a, __nv_bfloat16 b) {
    __nv_bfloat162 p; p.x = a; p.y = b;
    return *reinterpret_cast<uint32_t*>(&p);
}
// baseline-PTX tensor op (sm_80+): m16n8k16 bf16 row.col, fp32 accum
__device__ __forceinline__ void mma_bf16(float* d, const uint32_t* a,
                                         const uint32_t* b, const float* c) {
    asm volatile(
        "mma.sync.aligned.m16n8k16.row.col.f32.bf16.bf16.f32 "
        "{%0,%1,%2,%3}, {%4,%5,%6,%7}, {%8,%9}, {%10,%11,%12,%13};"
        : "=f"(d[0]), "=f"(d[1]), "=f"(d[2]), "=f"(d[3])
        : "r"(a[0]), "r"(a[1]), "r"(a[2]), "r"(a[3]),
          "r"(b[0]), "r"(b[1]),
          "f"(c[0]), "f"(c[1]), "f"(c[2]), "f"(c[3]));
}

// Kernel 1: grid 65. bid<64: hi/lo split + norms. bid==64: bucket fill.
__global__ void __launch_bounds__(NTHR)
prep_kernel(const float* __restrict__ z, const int* __restrict__ sid) {
    const int t = threadIdx.x;
    if (blockIdx.x < 64) {
        const int gid = blockIdx.x * NTHR + t;  // row*8 + chunk
        const int r = gid >> 3, c = gid & 7;
        float4 v = ((const float4*)z)[r * 8 + c];
        float s = v.x * v.x + v.y * v.y + v.z * v.z + v.w * v.w;
        s += __shfl_xor_sync(0xffffffffu, s, 1);
        s += __shfl_xor_sync(0xffffffffu, s, 2);
        s += __shfl_xor_sync(0xffffffffu, s, 4);
        if (c == 0) g_sq[r] = s;

        __nv_bfloat16 hx = __float2bfloat16(v.x), hy = __float2bfloat16(v.y);
        __nv_bfloat16 hz = __float2bfloat16(v.z), hw = __float2bfloat16(v.w);
        __nv_bfloat16 lx = __float2bfloat16(v.x - __bfloat162float(hx));
        __nv_bfloat16 ly = __float2bfloat16(v.y - __bfloat162float(hy));
        __nv_bfloat16 lz = __float2bfloat16(v.z - __bfloat162float(hz));
        __nv_bfloat16 lw = __float2bfloat16(v.w - __bfloat162float(hw));
        g_zhl[r * 32 + c * 2]          = bpack(hx, hy);
        g_zhl[r * 32 + c * 2 + 1]      = bpack(hz, hw);
        g_zhl[r * 32 + 16 + c * 2]     = bpack(lx, ly);
        g_zhl[r * 32 + 16 + c * 2 + 1] = bpack(lz, lw);
    } else {
        for (int j = t; j < BN; j += NTHR) {
            int id = sid[j];
            int slot = atomicAdd(&g_bcnt[id], 1);
            if (slot < BCAP) g_bkt[id * BCAP + slot] = j;
        }
    }
}

// Kernel 2: grid (16, 24).
//  y<16 : den tile 128x128 via mma.sync bf16 hi/lo; diagonal skipped by index.
//  y>=16: sparse num/valid via inverse buckets (fp32, warp per 2 rows).
// Last of 384 CTAs: final scalar reduction + scratch reset.
__global__ void __launch_bounds__(NTHR, 2)
main_kernel(const float* __restrict__ z,
            const int* __restrict__ knn,
            const int* __restrict__ sid,
            float* __restrict__ out) {
    __shared__ __align__(16) char s_a[MT * RS];
    __shared__ __align__(16) char s_b[NT * RS];
    __shared__ float s_pd[128][2];
    __shared__ float s_sqi[MT];
    __shared__ float s_sqj[NT];
    __shared__ bool s_last;

    const int t = threadIdx.x;
    const int w = t >> 5, lane = t & 31;
    const int gID = lane >> 2, tig = lane & 3;
    const int x = blockIdx.x, y = blockIdx.y;

    if (y < YT) {
        // ---- load tiles: A = rows [x*128,+128), B = rows [y*128,+128) ----
        const uint4* src = (const uint4*)g_zhl;   // 8 uint4 per 128B row
#pragma unroll
        for (int i = t; i < MT * 8; i += NTHR) {
            int row = i >> 3, u = i & 7;
            *(uint4*)(s_a + row * RS + u * 16) = src[(x * MT + row) * 8 + u];
            *(uint4*)(s_b + row * RS + u * 16) = src[(y * NT + row) * 8 + u];
        }
        if (t < MT) s_sqi[t] = g_sq[x * MT + t];
        else if (t < MT + NT) s_sqj[t - MT] = g_sq[y * NT + (t - MT)];
        __syncthreads();

        // ---- warp tile: wm in 0..3 (32 rows), wn in 0..1 (64 cols) ----
        const int wm = w & 3, wn = w >> 2;
        float acc[2][8][4];
#pragma unroll
        for (int mi = 0; mi < 2; mi++)
#pragma unroll
            for (int ni = 0; ni < 8; ni++)
#pragma unroll
                for (int q = 0; q < 4; q++) acc[mi][ni][q] = 0.f;

        // combos: 0 = hi*hi, 1 = hi*lo, 2 = lo*hi   (lo stored at +64B)
#pragma unroll
        for (int combo = 0; combo < 3; combo++) {
            const int aoff = (combo == 2) ? 64 : 0;
            const int boff = (combo == 1) ? 64 : 0;
#pragma unroll
            for (int kk = 0; kk < 2; kk++) {
                const int ka = aoff + kk * 32 + tig * 4;   // byte offset in row
                const int kb = boff + kk * 32 + tig * 4;
                uint32_t af[2][4];
#pragma unroll
                for (int mi = 0; mi < 2; mi++) {
                    const char* base = s_a + (wm * 32 + mi * 16 + gID) * RS;
                    af[mi][0] = *(const uint32_t*)(base + ka);
                    af[mi][1] = *(const uint32_t*)(base + 8 * RS + ka);
                    af[mi][2] = *(const uint32_t*)(base + ka + 16);
                    af[mi][3] = *(const uint32_t*)(base + 8 * RS + ka + 16);
                }
#pragma unroll
                for (int ni = 0; ni < 8; ni++) {
                    const char* bb = s_b + (wn * 64 + ni * 8 + gID) * RS;
                    uint32_t bf[2];
                    bf[0] = *(const uint32_t*)(bb + kb);
                    bf[1] = *(const uint32_t*)(bb + kb + 16);
                    mma_bf16(acc[0][ni], af[0], bf, acc[0][ni]);
                    mma_bf16(acc[1][ni], af[1], bf, acc[1][ni]);
                }
            }
        }

        // ---- epilogue: exp(-sqrt(d2)), skip diagonal, row sums ----
#pragma unroll
        for (int mi = 0; mi < 2; mi++) {
            const int lr0 = wm * 32 + mi * 16 + gID;
            const int lr1 = lr0 + 8;
            const int gi0 = x * MT + lr0, gi1 = x * MT + lr1;
            const float sq0 = s_sqi[lr0], sq1 = s_sqi[lr1];
            float rs0 = 0.f, rs1 = 0.f;
#pragma unroll
            for (int ni = 0; ni < 8; ni++) {
                const int cl = wn * 64 + ni * 8 + tig * 2;
                const int gj0 = y * NT + cl, gj1 = gj0 + 1;
                const float sa = s_sqj[cl], sb = s_sqj[cl + 1];
                float e;
                e = pair_e(acc[mi][ni][0], sq0 + sa); rs0 += (gj0 == gi0) ? 0.f : e;
                e = pair_e(acc[mi][ni][1], sq0 + sb); rs0 += (gj1 == gi0) ? 0.f : e;
                e = pair_e(acc[mi][ni][2], sq1 + sa); rs1 += (gj0 == gi1) ? 0.f : e;
                e = pair_e(acc[mi][ni][3], sq1 + sb); rs1 += (gj1 == gi1) ? 0.f : e;
            }
            rs0 += __shfl_xor_sync(0xffffffffu, rs0, 1);
            rs0 += __shfl_xor_sync(0xffffffffu, rs0, 2);
            rs1 += __shfl_xor_sync(0xffffffffu, rs1, 1);
            rs1 += __shfl_xor_sync(0xffffffffu, rs1, 2);
            if (tig == 0) { s_pd[lr0][wn] = rs0; s_pd[lr1][wn] = rs1; }
        }
        __syncthreads();
        if (t < MT) g_pden[y * BN + x * MT + t] = s_pd[t][0] + s_pd[t][1];
    } else {
        // ---- sparse num / valid: warp handles 2 rows ----
        const int ysp = y - YT;
#pragma unroll
        for (int rr = 0; rr < 2; rr++) {
            const int i = x * MT + ysp * 16 + w * 2 + rr;
            const int sidi = sid[i];
            int id = (lane < KNN) ? knn[sidi * KNN + lane] : -1;
            bool dup = false;
#pragma unroll
            for (int p = 0; p < KNN; p++) {
                int idp = __shfl_sync(0xffffffffu, id, p);
                dup = dup || (p < lane && idp == id);
            }
            float num = 0.f;
            bool found = false;
            if (lane < KNN && !dup) {
                int cnt = g_bcnt[id];
                if (cnt > BCAP) cnt = BCAP;
                if (cnt > 0) {
                    int jarr[BCAP];
                    for (int s2 = 0; s2 < cnt; s2++) jarr[s2] = g_bkt[id * BCAP + s2];
                    for (int a = 1; a < cnt; a++) {   // sort -> deterministic order
                        int v = jarr[a]; int b = a - 1;
                        while (b >= 0 && jarr[b] > v) { jarr[b + 1] = jarr[b]; b--; }
                        jarr[b + 1] = v;
                    }
                    for (int s2 = 0; s2 < cnt; s2++) {
                        int jj = jarr[s2];
                        if (jj != i) {
                            const float* zi = z + i * DD;
                            const float* zj = z + jj * DD;
                            float dot = 0.f;
#pragma unroll
                            for (int k = 0; k < DD; k++) dot = fmaf(zi[k], zj[k], dot);
                            num += pair_e(dot, g_sq[i] + g_sq[jj]);
                            found = true;
                        }
                    }
                }
            }
#pragma unroll
            for (int off = 16; off > 0; off >>= 1)
                num += __shfl_xor_sync(0xffffffffu, num, off);
            unsigned bal = __ballot_sync(0xffffffffu, found);
            if (lane == 0) {
                g_num[i] = num;
                g_any[i] = bal ? 1.f : 0.f;
            }
        }
    }

    // ---- last-block final reduction (deterministic) ----
    __threadfence();
    if (t == 0) {
        unsigned old = atomicAdd(&g_cnt, 1u);
        s_last = (old == NCTAS_ALL - 1);
    }
    __syncthreads();
    if (!s_last) return;

    __threadfence();
    float tot = 0.f, cnt = 0.f;
    for (int i = t; i < BN; i += NTHR) {
        float dv = 0.f;
#pragma unroll
        for (int yy = 0; yy < YT; yy++) dv += __ldcg(&g_pden[yy * BN + i]);
        float nv = __ldcg(&g_num[i]);
        bool valid = __ldcg(&g_any[i]) > 0.f;
        float sr = nv / dv;
        float loss = -__logf(sr + 1e-8f);
        tot += valid ? loss : 0.f;
        cnt += valid ? 1.f : 0.f;
    }
#pragma unroll
    for (int off = 16; off > 0; off >>= 1) {
        tot += __shfl_xor_sync(0xffffffffu, tot, off);
        cnt += __shfl_xor_sync(0xffffffffu, cnt, off);
    }
    if (lane == 0) { s_pd[w][0] = tot; s_pd[w][1] = cnt; }
    __syncthreads();
    if (t == 0) {
        float T = 0.f, C = 0.f;
#pragma unroll
        for (int ww = 0; ww < NTHR / 32; ww++) { T += s_pd[ww][0]; C += s_pd[ww][1]; }
        out[0] = (C > 0.f) ? (T / C) : 0.f;
        g_cnt = 0;
    }
    for (int i = t; i < NIDS; i += NTHR) g_bcnt[i] = 0;  // reset for next replay
}

extern "C" void kernel_launch(void* const* d_in, const int* in_sizes, int n_in,
                              void* d_out, int out_size) {
    const float* z   = (const float*)d_in[0];
    const int*   knn = (const int*)d_in[1];
    const int*   sid = (const int*)d_in[2];
    (void)in_sizes; (void)n_in; (void)out_size;

    prep_kernel<<<65, NTHR>>>(z, sid);
    main_kernel<<<dim3(XT, YT + SPY, 1), NTHR>>>(z, knn, sid, (float*)d_out);
}